// round 2
// baseline (speedup 1.0000x reference)
#include <cuda_runtime.h>
#include <cstdint>

// ---------------- problem constants ----------------
#define BB 16
#define TT 250
#define EE 512
#define HH 1024
#define VV 32000
#define H3 3072
#define MM (BB*TT)          // 4000

// ---------------- scratch (static device memory; no allocations) ----------------
__device__ __align__(16) float g_xproj[MM*H3];   // [4000,3072]
__device__ __align__(16) float g_hs[MM*HH];      // [4000,1024]  (m = b*T + t)
__device__ __align__(16) float g_h[2][BB*HH];    // double-buffered hidden state
__device__ unsigned g_cnt = 0;
__device__ unsigned g_sense = 0;

// ---------------- tf32 helpers ----------------
__device__ __forceinline__ unsigned f2tf(float f){
    unsigned u; asm("cvt.rna.tf32.f32 %0, %1;" : "=r"(u) : "f"(f)); return u;
}
__device__ __forceinline__ void mma_tf32(float* c,
    unsigned a0, unsigned a1, unsigned a2, unsigned a3,
    unsigned b0, unsigned b1){
    asm volatile("mma.sync.aligned.m16n8k8.row.col.f32.tf32.tf32.f32 "
        "{%0,%1,%2,%3},{%4,%5,%6,%7},{%8,%9},{%0,%1,%2,%3};"
        : "+f"(c[0]), "+f"(c[1]), "+f"(c[2]), "+f"(c[3])
        : "r"(a0), "r"(a1), "r"(a2), "r"(a3), "r"(b0), "r"(b1));
}
__device__ __forceinline__ float4 tf4(float4 v){
    v.x = __uint_as_float(f2tf(v.x));
    v.y = __uint_as_float(f2tf(v.y));
    v.z = __uint_as_float(f2tf(v.z));
    v.w = __uint_as_float(f2tf(v.w));
    return v;
}

// =====================================================================
// Generic tf32 GEMM:  C[M,N] = A[M,K] @ B[K,N] + bias[N]
// BM=128, BN=128, BK=32, 256 threads, 8 warps (4x2), warp tile 32x64.
// Operands are tf32-rounded ONCE at the SMEM store; the inner loop is
// pure LDS + HMMA.
// GATHER: A row m comes from emb_table[tokens[m]] (K = E).
// =====================================================================
#define BM 128
#define BN 128
#define BK 32
#define AS_LD 36      // BK + 4 pad  (conflict-free A frags)
#define BS_LD 136     // BN + 8 pad  (conflict-free B frags)
#define GEMM_SMEM ((2*BM*AS_LD + 2*BK*BS_LD)*4)

template<bool GATHER>
__global__ __launch_bounds__(256, 1)
void gemm_tf32_kernel(const float* __restrict__ A, const float* __restrict__ B,
                      const float* __restrict__ bias, float* __restrict__ C,
                      int M, int N, int K, const int* __restrict__ tokens)
{
    extern __shared__ float sm[];
    float* As = sm;                    // [2][BM][AS_LD]
    float* Bs = sm + 2*BM*AS_LD;       // [2][BK][BS_LD]

    const int tid  = threadIdx.x;
    const int lane = tid & 31;
    const int w    = tid >> 5;
    const int g    = lane >> 2;        // 0..7
    const int a    = lane & 3;         // 0..3
    const int wm   = (w >> 1) * 32;    // warp row offset in tile
    const int wn   = (w & 1) * 64;     // warp col offset in tile

    const int bm = blockIdx.x * BM;    // m is blockIdx.x -> concurrent blocks share B tiles via L2
    const int bn = blockIdx.y * BN;

    // loader indices
    const int arow = tid >> 3;             // 0..31
    const int acol = (tid & 7) * 4;        // 0..28
    const int brow = tid >> 5;             // 0..7
    const int bcol = lane * 4;             // 0..124

    float acc[2][8][4];
    #pragma unroll
    for (int i = 0; i < 2; i++)
        #pragma unroll
        for (int j = 0; j < 8; j++)
            #pragma unroll
            for (int q = 0; q < 4; q++) acc[i][j][q] = 0.f;

    const int KT = K / BK;
    float4 pa[4], pb[4];

    // ---- tile loaders (GMEM -> regs) ----
    auto loadA = [&](int kt){
        const int k0 = kt*BK + acol;
        #pragma unroll
        for (int i = 0; i < 4; i++){
            int m = bm + arow + i*32;
            if (m < M){
                const float* src;
                if (GATHER){ int tok = __ldg(&tokens[m]); src = A + (size_t)tok*K + k0; }
                else       { src = A + (size_t)m*K + k0; }
                pa[i] = *reinterpret_cast<const float4*>(src);
            } else {
                pa[i] = make_float4(0.f,0.f,0.f,0.f);
            }
        }
    };
    auto loadB = [&](int kt){
        #pragma unroll
        for (int i = 0; i < 4; i++){
            int k = kt*BK + brow + i*8;
            pb[i] = *reinterpret_cast<const float4*>(B + (size_t)k*N + bn + bcol);
        }
    };
    // ---- regs -> SMEM, tf32-rounded once here ----
    auto stsA = [&](int buf){
        #pragma unroll
        for (int i = 0; i < 4; i++){
            float* d = As + buf*BM*AS_LD + (arow + i*32)*AS_LD + acol;
            *reinterpret_cast<float4*>(d) = tf4(pa[i]);
        }
    };
    auto stsB = [&](int buf){
        #pragma unroll
        for (int i = 0; i < 4; i++){
            float* d = Bs + buf*BK*BS_LD + (brow + i*8)*BS_LD + bcol;
            *reinterpret_cast<float4*>(d) = tf4(pb[i]);
        }
    };
    auto compute = [&](int buf){
        const float* Ab  = As + buf*BM*AS_LD;
        const float* Bb2 = Bs + buf*BK*BS_LD;
        #pragma unroll
        for (int ks = 0; ks < 4; ks++){
            const int kk = ks*8;
            unsigned Af[2][4];
            #pragma unroll
            for (int mt = 0; mt < 2; mt++){
                const float* ap = Ab + (wm + mt*16)*AS_LD + kk;
                Af[mt][0] = __float_as_uint(ap[(g    )*AS_LD + a    ]);
                Af[mt][1] = __float_as_uint(ap[(g + 8)*AS_LD + a    ]);
                Af[mt][2] = __float_as_uint(ap[(g    )*AS_LD + a + 4]);
                Af[mt][3] = __float_as_uint(ap[(g + 8)*AS_LD + a + 4]);
            }
            #pragma unroll
            for (int nt = 0; nt < 8; nt++){
                const float* bp = Bb2 + kk*BS_LD + wn + nt*8 + g;
                unsigned b0 = __float_as_uint(bp[(a    )*BS_LD]);
                unsigned b1 = __float_as_uint(bp[(a + 4)*BS_LD]);
                mma_tf32(acc[0][nt], Af[0][0],Af[0][1],Af[0][2],Af[0][3], b0, b1);
                mma_tf32(acc[1][nt], Af[1][0],Af[1][1],Af[1][2],Af[1][3], b0, b1);
            }
        }
    };

    // ---- pipelined main loop ----
    loadA(0); loadB(0);
    stsA(0);  stsB(0);
    __syncthreads();
    for (int kt = 0; kt < KT; kt++){
        if (kt + 1 < KT){ loadA(kt+1); loadB(kt+1); }
        compute(kt & 1);
        if (kt + 1 < KT){
            stsA((kt+1) & 1); stsB((kt+1) & 1);
            __syncthreads();
        }
    }

    // ---- epilogue: +bias, write float2 pairs ----
    #pragma unroll
    for (int mt = 0; mt < 2; mt++){
        #pragma unroll
        for (int nt = 0; nt < 8; nt++){
            int col  = bn + wn + nt*8 + 2*a;
            float bz0 = __ldg(&bias[col]);
            float bz1 = __ldg(&bias[col+1]);
            int row0 = bm + wm + mt*16 + g;
            if (row0 < M){
                float2 v = make_float2(acc[mt][nt][0] + bz0, acc[mt][nt][1] + bz1);
                *reinterpret_cast<float2*>(&C[(size_t)row0*N + col]) = v;
            }
            int row1 = row0 + 8;
            if (row1 < M){
                float2 v = make_float2(acc[mt][nt][2] + bz0, acc[mt][nt][3] + bz1);
                *reinterpret_cast<float2*>(&C[(size_t)row1*N + col]) = v;
            }
        }
    }
}

// =====================================================================
// Persistent GRU scan kernel. 128 blocks, 256 threads.
// Block b owns 8 hidden columns j0..j0+7 (24 U columns: z|r|h slices),
// U slice held tf32-rounded in SMEM for all 250 steps.
// Per step: load h (64KB) -> 8-warp k-split tf32 mma (hi/lo split of h
// for ~fp32 accuracy) -> smem reduce -> gates -> write h_new + hs[t]
// -> grid barrier (sense-reversing; even #flips -> graph-replay safe).
// =====================================================================
#define SCAN_NBLK 128
#define U_LD 26                          // 24 + 2 pad
#define H_LD 1028                        // 1024 + 4 pad
#define SCAN_SMEM ((HH*U_LD + BB*H_LD + 8*3*BB*8)*4)

__global__ __launch_bounds__(256, 1)
void gru_scan_kernel(const float* __restrict__ xproj,
                     const float* __restrict__ h0,
                     const float* __restrict__ U,
                     const float* __restrict__ brec)
{
    extern __shared__ float sm[];
    float* U_s = sm;                     // [1024][U_LD]
    float* h_s = sm + HH*U_LD;           // [16][H_LD]
    float* red = h_s + BB*H_LD;          // [8 warps][3 gates][16][8]
    __shared__ unsigned bar_phase;

    const int tid  = threadIdx.x;
    const int lane = tid & 31;
    const int w    = tid >> 5;           // 0..7
    const int g    = lane >> 2;
    const int a    = lane & 3;
    const int j0   = blockIdx.x * 8;

    if (tid == 0) bar_phase = 0;

    // one-time: load this block's U slice (tf32-rounded) into SMEM
    for (int e = tid; e < HH*24; e += 256){
        int k = e / 24, c = e - k*24;
        int gate = c >> 3, jj = c & 7;
        float v = U[(size_t)k*H3 + gate*HH + j0 + jj];
        U_s[k*U_LD + c] = __uint_as_float(f2tf(v));
    }
    __syncthreads();

    for (int t = 0; t < TT; t++){
        // ---- broadcast-load full h into SMEM (vectorized) ----
        const float* hsrc = (t == 0) ? h0 : g_h[(t-1) & 1];
        #pragma unroll
        for (int i = 0; i < 16; i++){
            int e = (i*256 + tid)*4;
            int b = e >> 10, k = e & 1023;
            float4 v = *reinterpret_cast<const float4*>(hsrc + e);
            *reinterpret_cast<float4*>(&h_s[b*H_LD + k]) = v;
        }
        __syncthreads();

        // ---- k-split tf32 mma, hi/lo split of h for fp32-accurate A ----
        float c[3][4];
        #pragma unroll
        for (int nt = 0; nt < 3; nt++)
            #pragma unroll
            for (int q = 0; q < 4; q++) c[nt][q] = 0.f;

        const int kbase = w * 128;
        #pragma unroll 4
        for (int ks = 0; ks < 16; ks++){
            int k = kbase + ks*8;
            float f0 = h_s[(g    )*H_LD + k + a    ];
            float f1 = h_s[(g + 8)*H_LD + k + a    ];
            float f2 = h_s[(g    )*H_LD + k + a + 4];
            float f3 = h_s[(g + 8)*H_LD + k + a + 4];
            unsigned h0b = f2tf(f0), h1b = f2tf(f1), h2b = f2tf(f2), h3b = f2tf(f3);
            unsigned l0 = f2tf(f0 - __uint_as_float(h0b));
            unsigned l1 = f2tf(f1 - __uint_as_float(h1b));
            unsigned l2 = f2tf(f2 - __uint_as_float(h2b));
            unsigned l3 = f2tf(f3 - __uint_as_float(h3b));
            #pragma unroll
            for (int nt = 0; nt < 3; nt++){
                unsigned b0 = __float_as_uint(U_s[(k + a    )*U_LD + nt*8 + g]);
                unsigned b1 = __float_as_uint(U_s[(k + a + 4)*U_LD + nt*8 + g]);
                mma_tf32(c[nt], h0b, h1b, h2b, h3b, b0, b1);
                mma_tf32(c[nt], l0,  l1,  l2,  l3,  b0, b1);
            }
        }

        // ---- store per-warp partials ----
        #pragma unroll
        for (int nt = 0; nt < 3; nt++){
            float* r = red + ((w*3 + nt)*BB)*8;
            r[(g    )*8 + 2*a    ] = c[nt][0];
            r[(g    )*8 + 2*a + 1] = c[nt][1];
            r[(g + 8)*8 + 2*a    ] = c[nt][2];
            r[(g + 8)*8 + 2*a + 1] = c[nt][3];
        }
        __syncthreads();

        // ---- gates (128 threads: one per (b, jj)) ----
        if (tid < 128){
            int b = tid >> 3, jj = tid & 7;
            float rec[3];
            #pragma unroll
            for (int nt = 0; nt < 3; nt++){
                float s = __ldg(&brec[nt*HH + j0 + jj]);
                #pragma unroll
                for (int ww = 0; ww < 8; ww++)
                    s += red[((ww*3 + nt)*BB + b)*8 + jj];
                rec[nt] = s;
            }
            size_t base = (size_t)(b*TT + t) * H3;
            float xz = xproj[base +          j0 + jj];
            float xr = xproj[base +   HH   + j0 + jj];
            float xh = xproj[base + 2*HH   + j0 + jj];
            float z  = 1.f / (1.f + expf(-(xz + rec[0])));
            float r  = 1.f / (1.f + expf(-(xr + rec[1])));
            float hh = tanhf(xh + r * rec[2]);
            float hold = h_s[b*H_LD + j0 + jj];
            float hn = z * hold + (1.f - z) * hh;
            g_h[t & 1][b*HH + j0 + jj] = hn;
            g_hs[(size_t)(b*TT + t)*HH + j0 + jj] = hn;
        }

        // ---- grid-wide barrier (sense-reversing; 250 flips -> state restored) ----
        __syncthreads();
        if (tid == 0){
            unsigned exp = bar_phase ^ 1u;
            __threadfence();
            if (atomicAdd(&g_cnt, 1u) == SCAN_NBLK - 1){
                atomicExch(&g_cnt, 0u);
                __threadfence();
                atomicExch(&g_sense, exp);
            } else {
                while (atomicAdd(&g_sense, 0u) != exp) { __nanosleep(64); }
            }
            __threadfence();
            bar_phase = exp;
        }
        __syncthreads();
    }
}

// =====================================================================
// host launcher
// =====================================================================
extern "C" void kernel_launch(void* const* d_in, const int* in_sizes, int n_in,
                              void* d_out, int out_size)
{
    const int*   tok  = (const int*)  d_in[0];   // [16,250]
    const float* h0   = (const float*)d_in[1];   // [16,1024]
    const float* emb  = (const float*)d_in[2];   // [32000,512]
    const float* W    = (const float*)d_in[3];   // [512,3072]
    const float* U    = (const float*)d_in[4];   // [1024,3072]
    const float* b    = (const float*)d_in[5];   // [2,3072]
    const float* Wo   = (const float*)d_in[6];   // [1024,32000]
    const float* bo   = (const float*)d_in[7];   // [32000]
    float* out = (float*)d_out;                  // [16,250,32000] f32

    float* xproj; cudaGetSymbolAddress((void**)&xproj, g_xproj);
    float* hs;    cudaGetSymbolAddress((void**)&hs,    g_hs);

    cudaFuncSetAttribute(gemm_tf32_kernel<true>,
        cudaFuncAttributeMaxDynamicSharedMemorySize, GEMM_SMEM);
    cudaFuncSetAttribute(gemm_tf32_kernel<false>,
        cudaFuncAttributeMaxDynamicSharedMemorySize, GEMM_SMEM);
    cudaFuncSetAttribute(gru_scan_kernel,
        cudaFuncAttributeMaxDynamicSharedMemorySize, SCAN_SMEM);

    dim3 blk(256);

    // 1) x_proj = gather(emb, tokens) @ W + b[0]
    {
        dim3 grid((MM + BM - 1)/BM, H3/BN);   // 32 x 24
        gemm_tf32_kernel<true><<<grid, blk, GEMM_SMEM>>>(
            emb, W, b, xproj, MM, H3, EE, tok);
    }

    // 2) GRU scan over T=250
    gru_scan_kernel<<<SCAN_NBLK, blk, SCAN_SMEM>>>(xproj, h0, U, b + H3);

    // 3) logits = hs @ Wo + bo
    {
        dim3 grid((MM + BM - 1)/BM, VV/BN);   // 32 x 250
        gemm_tf32_kernel<false><<<grid, blk, GEMM_SMEM>>>(
            hs, Wo, bo, out, MM, VV, HH, nullptr);
    }
}

// round 8
// speedup vs baseline: 1.0402x; 1.0402x over previous
#include <cuda_runtime.h>
#include <cstdint>

// ---------------- problem constants ----------------
#define BB 16
#define TT 250
#define EE 512
#define HH 1024
#define VV 32000
#define H3 3072
#define MM (BB*TT)          // 4000

// ---------------- scratch (static device memory; no allocations) ----------------
__device__ __align__(16) float g_xproj[MM*H3];        // [4000,3072]
__device__ __align__(16) float g_hs[MM*HH];           // [4000,1024] tf32-rounded
__device__ __align__(16) float g_h[2][BB*HH];         // double-buffered hidden state
__device__ __align__(16) float g_embR[(size_t)VV*EE]; // emb, tf32-rounded
__device__ __align__(16) float g_WR [EE*H3];          // W,   tf32-rounded
__device__ __align__(16) float g_WoR[(size_t)HH*VV];  // Wo,  tf32-rounded
__device__ unsigned g_cnt = 0;
__device__ unsigned g_sense = 0;

// ---------------- helpers ----------------
__device__ __forceinline__ unsigned f2tf(float f){
    unsigned u; asm("cvt.rna.tf32.f32 %0, %1;" : "=r"(u) : "f"(f)); return u;
}
__device__ __forceinline__ void mma_tf32(float* c,
    unsigned a0, unsigned a1, unsigned a2, unsigned a3,
    unsigned b0, unsigned b1){
    asm volatile("mma.sync.aligned.m16n8k8.row.col.f32.tf32.tf32.f32 "
        "{%0,%1,%2,%3},{%4,%5,%6,%7},{%8,%9},{%0,%1,%2,%3};"
        : "+f"(c[0]), "+f"(c[1]), "+f"(c[2]), "+f"(c[3])
        : "r"(a0), "r"(a1), "r"(a2), "r"(a3), "r"(b0), "r"(b1));
}
__device__ __forceinline__ uint32_t smem_u32(const void* p){
    uint32_t a;
    asm("{ .reg .u64 t; cvta.to.shared.u64 t, %1; cvt.u32.u64 %0, t; }" : "=r"(a) : "l"(p));
    return a;
}
__device__ __forceinline__ void cpa16(uint32_t dst, const void* src, int sz){
    asm volatile("cp.async.cg.shared.global [%0], [%1], 16, %2;" :: "r"(dst), "l"(src), "r"(sz));
}
__device__ __forceinline__ void cpa_commit(){ asm volatile("cp.async.commit_group;"); }
template<int N> __device__ __forceinline__ void cpa_wait(){ asm volatile("cp.async.wait_group %0;" :: "n"(N)); }

// =====================================================================
// Elementwise tf32 pre-round: dst[i] = rna_tf32(src[i]).  n % 4 == 0.
// =====================================================================
__global__ void round_tf32(const float* __restrict__ src, float* __restrict__ dst, size_t n)
{
    size_t stride = (size_t)gridDim.x * blockDim.x * 4;
    for (size_t i = ((size_t)blockIdx.x * blockDim.x + threadIdx.x) * 4; i < n; i += stride){
        float4 v = *reinterpret_cast<const float4*>(src + i);
        v.x = __uint_as_float(f2tf(v.x));
        v.y = __uint_as_float(f2tf(v.y));
        v.z = __uint_as_float(f2tf(v.z));
        v.w = __uint_as_float(f2tf(v.w));
        *reinterpret_cast<float4*>(dst + i) = v;
    }
}

// =====================================================================
// 4-stage cp.async pipelined tf32 GEMM:  C[M,N] = A[M,K] @ B[K,N] + bias[N]
// BM=128, BN=128, BK=32, 256 threads, 8 warps (4x2), warp tile 32x64.
// Operands must be PRE-ROUNDED to tf32 (cp.async cannot convert).
// GATHER: A row m comes from A[tokens[m]] (embedding, K = E).
// =====================================================================
#define BM 128
#define BN 128
#define BK 32
#define AS_LD 36      // BK + 4 pad  (conflict-free A frags)
#define BS_LD 136     // BN + 8 pad  (conflict-free B frags)
#define STG_F (BM*AS_LD + BK*BS_LD)          // 8960 floats per stage
#define GEMM_SMEM (4*STG_F*4)                // 143360 bytes

template<bool GATHER>
__global__ __launch_bounds__(256, 1)
void gemm_pipe(const float* __restrict__ A, const float* __restrict__ B,
               const float* __restrict__ bias, float* __restrict__ C,
               int M, int N, int K, const int* __restrict__ tokens)
{
    extern __shared__ float sm[];
    const uint32_t sb = smem_u32(sm);

    const int tid  = threadIdx.x;
    const int lane = tid & 31;
    const int w    = tid >> 5;
    const int g    = lane >> 2;        // 0..7
    const int a    = lane & 3;         // 0..3
    const int wm   = (w >> 1) * 32;    // warp row offset
    const int wn   = (w & 1) * 64;     // warp col offset

    const int bm = blockIdx.x * BM;    // m fastest -> blocks in a wave share B tiles via L2
    const int bn = blockIdx.y * BN;
    const int KT = K / BK;

    float acc[2][8][4];
    #pragma unroll
    for (int i = 0; i < 2; i++)
        #pragma unroll
        for (int j = 0; j < 8; j++)
            #pragma unroll
            for (int q = 0; q < 4; q++) acc[i][j][q] = 0.f;

    // ---- issue one k-tile stage of cp.async (A: 1024 chunks, B: 1024 chunks) ----
    auto issue = [&](int kt){
        const int s = kt & 3;
        const uint32_t Ab = sb + s*STG_F*4;
        const uint32_t Bb = Ab + BM*AS_LD*4;
        const int k0 = kt * BK;
        #pragma unroll
        for (int i = 0; i < 4; i++){
            int idx = tid + i*256;             // 0..1023
            int row = idx >> 3, c4 = (idx & 7)*4;
            int m = bm + row;
            const float* src = A;
            int sz = 0;
            if (GATHER){
                if (m < M){ int tok = __ldg(&tokens[m]);
                            src = A + (size_t)tok*K + k0 + c4; sz = 16; }
            } else {
                if (m < M){ src = A + (size_t)m*K + k0 + c4; sz = 16; }
            }
            cpa16(Ab + (row*AS_LD + c4)*4, src, sz);
        }
        #pragma unroll
        for (int i = 0; i < 4; i++){
            int idx = tid + i*256;             // 0..1023
            int row = idx >> 5, c4 = (idx & 31)*4;
            const float* src = B + (size_t)(k0 + row)*N + bn + c4;
            cpa16(Bb + (row*BS_LD + c4)*4, src, 16);
        }
    };

    // ---- compute one staged k-tile ----
    auto compute = [&](int s){
        const float* Ab  = sm + s*STG_F;
        const float* Bb2 = Ab + BM*AS_LD;
        #pragma unroll
        for (int ks = 0; ks < 4; ks++){
            const int kk = ks*8;
            unsigned Af[2][4];
            #pragma unroll
            for (int mt = 0; mt < 2; mt++){
                const float* ap = Ab + (wm + mt*16)*AS_LD + kk;
                Af[mt][0] = __float_as_uint(ap[(g    )*AS_LD + a    ]);
                Af[mt][1] = __float_as_uint(ap[(g + 8)*AS_LD + a    ]);
                Af[mt][2] = __float_as_uint(ap[(g    )*AS_LD + a + 4]);
                Af[mt][3] = __float_as_uint(ap[(g + 8)*AS_LD + a + 4]);
            }
            #pragma unroll
            for (int nt = 0; nt < 8; nt++){
                const float* bp = Bb2 + kk*BS_LD + wn + nt*8 + g;
                unsigned b0 = __float_as_uint(bp[(a    )*BS_LD]);
                unsigned b1 = __float_as_uint(bp[(a + 4)*BS_LD]);
                mma_tf32(acc[0][nt], Af[0][0],Af[0][1],Af[0][2],Af[0][3], b0, b1);
                mma_tf32(acc[1][nt], Af[1][0],Af[1][1],Af[1][2],Af[1][3], b0, b1);
            }
        }
    };

    // ---- pipeline: 3 stages in flight; exactly one commit per loop iter ----
    issue(0); cpa_commit();
    issue(1); cpa_commit();
    issue(2); cpa_commit();
    for (int kt = 0; kt < KT; kt++){
        cpa_wait<2>();          // stage kt's group complete
        __syncthreads();        // make it visible block-wide
        compute(kt & 3);
        __syncthreads();        // everyone done reading stage kt
        if (kt + 3 < KT) issue(kt + 3);
        cpa_commit();           // uniform group count (may be empty)
    }

    // ---- epilogue: +bias, write float2 pairs ----
    #pragma unroll
    for (int mt = 0; mt < 2; mt++){
        #pragma unroll
        for (int nt = 0; nt < 8; nt++){
            int col  = bn + wn + nt*8 + 2*a;
            float bz0 = __ldg(&bias[col]);
            float bz1 = __ldg(&bias[col+1]);
            int row0 = bm + wm + mt*16 + g;
            if (row0 < M){
                float2 v = make_float2(acc[mt][nt][0] + bz0, acc[mt][nt][1] + bz1);
                *reinterpret_cast<float2*>(&C[(size_t)row0*N + col]) = v;
            }
            int row1 = row0 + 8;
            if (row1 < M){
                float2 v = make_float2(acc[mt][nt][2] + bz0, acc[mt][nt][3] + bz1);
                *reinterpret_cast<float2*>(&C[(size_t)row1*N + col]) = v;
            }
        }
    }
}

// =====================================================================
// Persistent GRU scan kernel (proven in R2). 128 blocks, 256 threads.
// Block owns 8 hidden cols; U slice tf32-rounded in SMEM for all steps.
// hi/lo tf32 split of h keeps the recurrence ~fp32 accurate.
// Stores hs tf32-pre-rounded (A operand of GEMM3).
// =====================================================================
#define SCAN_NBLK 128
#define U_LD 26
#define H_LD 1028
#define SCAN_SMEM ((HH*U_LD + BB*H_LD + 8*3*BB*8)*4)

__global__ __launch_bounds__(256, 1)
void gru_scan_kernel(const float* __restrict__ xproj,
                     const float* __restrict__ h0,
                     const float* __restrict__ U,
                     const float* __restrict__ brec)
{
    extern __shared__ float sm[];
    float* U_s = sm;
    float* h_s = sm + HH*U_LD;
    float* red = h_s + BB*H_LD;
    __shared__ unsigned bar_phase;

    const int tid  = threadIdx.x;
    const int lane = tid & 31;
    const int w    = tid >> 5;
    const int g    = lane >> 2;
    const int a    = lane & 3;
    const int j0   = blockIdx.x * 8;

    if (tid == 0) bar_phase = 0;

    for (int e = tid; e < HH*24; e += 256){
        int k = e / 24, c = e - k*24;
        int gate = c >> 3, jj = c & 7;
        float v = U[(size_t)k*H3 + gate*HH + j0 + jj];
        U_s[k*U_LD + c] = __uint_as_float(f2tf(v));
    }
    __syncthreads();

    for (int t = 0; t < TT; t++){
        const float* hsrc = (t == 0) ? h0 : g_h[(t-1) & 1];
        #pragma unroll
        for (int i = 0; i < 16; i++){
            int e = (i*256 + tid)*4;
            int b = e >> 10, k = e & 1023;
            float4 v = *reinterpret_cast<const float4*>(hsrc + e);
            *reinterpret_cast<float4*>(&h_s[b*H_LD + k]) = v;
        }
        __syncthreads();

        float c[3][4];
        #pragma unroll
        for (int nt = 0; nt < 3; nt++)
            #pragma unroll
            for (int q = 0; q < 4; q++) c[nt][q] = 0.f;

        const int kbase = w * 128;
        #pragma unroll 4
        for (int ks = 0; ks < 16; ks++){
            int k = kbase + ks*8;
            float f0 = h_s[(g    )*H_LD + k + a    ];
            float f1 = h_s[(g + 8)*H_LD + k + a    ];
            float f2 = h_s[(g    )*H_LD + k + a + 4];
            float f3 = h_s[(g + 8)*H_LD + k + a + 4];
            unsigned h0b = f2tf(f0), h1b = f2tf(f1), h2b = f2tf(f2), h3b = f2tf(f3);
            unsigned l0 = f2tf(f0 - __uint_as_float(h0b));
            unsigned l1 = f2tf(f1 - __uint_as_float(h1b));
            unsigned l2 = f2tf(f2 - __uint_as_float(h2b));
            unsigned l3 = f2tf(f3 - __uint_as_float(h3b));
            #pragma unroll
            for (int nt = 0; nt < 3; nt++){
                unsigned b0 = __float_as_uint(U_s[(k + a    )*U_LD + nt*8 + g]);
                unsigned b1 = __float_as_uint(U_s[(k + a + 4)*U_LD + nt*8 + g]);
                mma_tf32(c[nt], h0b, h1b, h2b, h3b, b0, b1);
                mma_tf32(c[nt], l0,  l1,  l2,  l3,  b0, b1);
            }
        }

        #pragma unroll
        for (int nt = 0; nt < 3; nt++){
            float* r = red + ((w*3 + nt)*BB)*8;
            r[(g    )*8 + 2*a    ] = c[nt][0];
            r[(g    )*8 + 2*a + 1] = c[nt][1];
            r[(g + 8)*8 + 2*a    ] = c[nt][2];
            r[(g + 8)*8 + 2*a + 1] = c[nt][3];
        }
        __syncthreads();

        if (tid < 128){
            int b = tid >> 3, jj = tid & 7;
            float rec[3];
            #pragma unroll
            for (int nt = 0; nt < 3; nt++){
                float s = __ldg(&brec[nt*HH + j0 + jj]);
                #pragma unroll
                for (int ww = 0; ww < 8; ww++)
                    s += red[((ww*3 + nt)*BB + b)*8 + jj];
                rec[nt] = s;
            }
            size_t base = (size_t)(b*TT + t) * H3;
            float xz = xproj[base +          j0 + jj];
            float xr = xproj[base +   HH   + j0 + jj];
            float xh = xproj[base + 2*HH   + j0 + jj];
            float z  = 1.f / (1.f + expf(-(xz + rec[0])));
            float r  = 1.f / (1.f + expf(-(xr + rec[1])));
            float hh = tanhf(xh + r * rec[2]);
            float hold = h_s[b*H_LD + j0 + jj];
            float hn = z * hold + (1.f - z) * hh;
            g_h[t & 1][b*HH + j0 + jj] = hn;
            g_hs[(size_t)(b*TT + t)*HH + j0 + jj] = __uint_as_float(f2tf(hn));
        }

        __syncthreads();
        if (tid == 0){
            unsigned exp = bar_phase ^ 1u;
            __threadfence();
            if (atomicAdd(&g_cnt, 1u) == SCAN_NBLK - 1){
                atomicExch(&g_cnt, 0u);
                __threadfence();
                atomicExch(&g_sense, exp);
            } else {
                while (atomicAdd(&g_sense, 0u) != exp) { __nanosleep(64); }
            }
            __threadfence();
            bar_phase = exp;
        }
        __syncthreads();
    }
}

// =====================================================================
// host launcher
// =====================================================================
extern "C" void kernel_launch(void* const* d_in, const int* in_sizes, int n_in,
                              void* d_out, int out_size)
{
    const int*   tok  = (const int*)  d_in[0];   // [16,250]
    const float* h0   = (const float*)d_in[1];   // [16,1024]
    const float* emb  = (const float*)d_in[2];   // [32000,512]
    const float* W    = (const float*)d_in[3];   // [512,3072]
    const float* U    = (const float*)d_in[4];   // [1024,3072]
    const float* b    = (const float*)d_in[5];   // [2,3072]
    const float* Wo   = (const float*)d_in[6];   // [1024,32000]
    const float* bo   = (const float*)d_in[7];   // [32000]
    float* out = (float*)d_out;                  // [16,250,32000] f32

    float* xproj; cudaGetSymbolAddress((void**)&xproj, g_xproj);
    float* hs;    cudaGetSymbolAddress((void**)&hs,    g_hs);
    float* embR;  cudaGetSymbolAddress((void**)&embR,  g_embR);
    float* WR;    cudaGetSymbolAddress((void**)&WR,    g_WR);
    float* WoR;   cudaGetSymbolAddress((void**)&WoR,   g_WoR);

    cudaFuncSetAttribute(gemm_pipe<true>,
        cudaFuncAttributeMaxDynamicSharedMemorySize, GEMM_SMEM);
    cudaFuncSetAttribute(gemm_pipe<false>,
        cudaFuncAttributeMaxDynamicSharedMemorySize, GEMM_SMEM);
    cudaFuncSetAttribute(gru_scan_kernel,
        cudaFuncAttributeMaxDynamicSharedMemorySize, SCAN_SMEM);

    // 0) tf32 pre-round of GEMM operands (cp.async cannot convert)
    round_tf32<<<1184, 256>>>(emb, embR, (size_t)VV*EE);
    round_tf32<<<1184, 256>>>(W,   WR,   (size_t)EE*H3);
    round_tf32<<<1184, 256>>>(Wo,  WoR,  (size_t)HH*VV);

    // 1) x_proj = gather(embR, tokens) @ WR + b[0]
    {
        dim3 grid((MM + BM - 1)/BM, H3/BN);   // 32 x 24
        gemm_pipe<true><<<grid, 256, GEMM_SMEM>>>(embR, WR, b, xproj, MM, H3, EE, tok);
    }

    // 2) GRU scan over T=250
    gru_scan_kernel<<<SCAN_NBLK, 256, SCAN_SMEM>>>(xproj, h0, U, b + H3);

    // 3) logits = hs @ WoR + bo
    {
        dim3 grid((MM + BM - 1)/BM, VV/BN);   // 32 x 250
        gemm_pipe<false><<<grid, 256, GEMM_SMEM>>>(hs, WoR, bo, out, MM, VV, HH, nullptr);
    }
}